// round 6
// baseline (speedup 1.0000x reference)
#include <cuda_runtime.h>
#include <cstdint>

#define NB 8
#define NN 4096
#define NM 1024
#define ND 256

// ---------------- scratch (device globals; no runtime allocation) ----------------
static constexpr size_t OFF_WHT = 0;
static constexpr size_t OFF_WLT = OFF_WHT + (size_t)ND * ND;   // WlT then WgT contiguous (512x256)
static constexpr size_t OFF_WGT = OFF_WLT + (size_t)ND * ND;
static constexpr size_t OFF_BLG = OFF_WGT + (size_t)ND * ND;   // concat bias [bl|bg], 512
static constexpr size_t OFF_H   = OFF_BLG + 512;
static constexpr size_t OFF_L   = OFF_H  + (size_t)NB * NN * ND;  // L then G contiguous
static constexpr size_t OFF_G   = OFF_L  + (size_t)NB * NM * ND;
static constexpr size_t OFF_GT  = OFF_G  + (size_t)NB * NM * ND;
static constexpr size_t OFF_S   = OFF_GT + (size_t)NB * ND * NM;
static constexpr size_t SCRATCH_TOTAL = OFF_S + (size_t)NB * NN * NM;

__device__ float g_scratch[SCRATCH_TOTAL];

// ---------------- helpers ----------------
__device__ __forceinline__ uint32_t f2tf(float x) {
    uint32_t r;
    asm("cvt.rna.tf32.f32 %0, %1;" : "=r"(r) : "f"(x));
    return r;
}

#define MMA8(d, a, b)                                                          \
    asm volatile(                                                              \
        "mma.sync.aligned.m16n8k8.row.col.f32.tf32.tf32.f32 "                  \
        "{%0,%1,%2,%3},{%4,%5,%6,%7},{%8,%9},{%0,%1,%2,%3};\n"                 \
        : "+f"((d)[0]), "+f"((d)[1]), "+f"((d)[2]), "+f"((d)[3])               \
        : "r"((a)[0]), "r"((a)[1]), "r"((a)[2]), "r"((a)[3]),                  \
          "r"((b)[0]), "r"((b)[1]))

// ---------------- weight transpose + bias concat ----------------
__global__ void transpose_w_k(const float* __restrict__ Wh,
                              const float* __restrict__ Wl,
                              const float* __restrict__ Wg,
                              const float* __restrict__ bl,
                              const float* __restrict__ bg,
                              float* __restrict__ wht,
                              float* __restrict__ wlt,
                              float* __restrict__ wgt,
                              float* __restrict__ blg) {
    int i = blockIdx.x * blockDim.x + threadIdx.x;  // 65536 total
    int n = i >> 8, k = i & 255;
    wht[i] = Wh[k * ND + n];
    wlt[i] = Wl[k * ND + n];
    wgt[i] = Wg[k * ND + n];
    if (i < 512) blg[i] = (i < 256) ? bl[i] : bg[i - 256];
}

// ---------------- G transpose: GT[b][d][m] = G[b][m][d] ----------------
__global__ void transpose_g_k(const float* __restrict__ G, float* __restrict__ GT) {
    __shared__ float t[32][33];
    int b = blockIdx.z;
    int m0 = blockIdx.x * 32, d0 = blockIdx.y * 32;
    const float* src = G + (size_t)b * NM * ND;
    float* dst = GT + (size_t)b * ND * NM;
    int x = threadIdx.x, y = threadIdx.y;
#pragma unroll
    for (int i = 0; i < 32; i += 8) t[y + i][x] = src[(size_t)(m0 + y + i) * ND + d0 + x];
    __syncthreads();
#pragma unroll
    for (int i = 0; i < 32; i += 8) dst[(size_t)(d0 + y + i) * NM + m0 + x] = t[x][y + i];
}

// ---------------- TT GEMM, double-buffered smem + register prefetch ----------------
// C[row][col] = sum_k A[row][k] * Bsrc[col][k].
// tf32 hi/lo conversion at cooperative smem STORE (amortized; inner loop = pure LDS+MMA).
// Pipeline per K-step: LDG t+1 -> regs | MMA tile t (buf t&1) | cvt+STS -> buf (t+1)&1 | 1 sync.
// SPLIT: 3-MMA split-tf32. BIAS: +bias[col]. RESID: +R[row][col].
// SEG: cols 0..255 -> Cptr, 256..511 -> Cptr + NB*NM*ND (fused L/G output).
template <bool SPLIT, bool BIAS, bool RESID, bool SEG>
__global__ void __launch_bounds__(256)
gemm_tt(const float* __restrict__ Aptr, const float* __restrict__ Bptr,
        const float* __restrict__ bias, const float* __restrict__ Rptr,
        float* __restrict__ Cptr, int K, int Ncols,
        long long sA, long long sB, long long sC) {
    constexpr int BM = 128, BN = 128, BK = 16, LDSR = 20;
    constexpr int ARR = BM * LDSR;            // u32 per array (2560)
    constexpr int NARR = SPLIT ? 4 : 2;       // As,Bs[,Al,Bl]
    constexpr int STAGE = NARR * ARR;
    extern __shared__ uint32_t sm[];

    int tid = threadIdx.x;
    int lane = tid & 31, wid = tid >> 5;
    int wm = wid >> 1, wn = wid & 1;     // 4x2 warp grid; warp tile 32x64
    int grp = lane >> 2, tq = lane & 3;  // mma fragment coords

    long long zb = blockIdx.z;
    const float* A = Aptr + zb * sA + (long long)blockIdx.x * BM * K;
    const float* Bm = Bptr + zb * sB + (long long)blockIdx.y * BN * K;

    float acc[2][8][4];
#pragma unroll
    for (int i = 0; i < 2; i++)
#pragma unroll
        for (int j = 0; j < 8; j++)
#pragma unroll
            for (int q = 0; q < 4; q++) acc[i][j][q] = 0.f;

    const int nk = K / BK;
    float4 va[2], vb[2];  // register prefetch (A,B tile: 2 float4 each per thread)

    // per-thread tile coords (fixed): 512 float4 per 128x16 tile, 2 per thread
    int rr0 = tid >> 2, cc0 = (tid & 3) * 4;
    int rr1 = (tid + 256) >> 2, cc1 = ((tid + 256) & 3) * 4;

    // ---- prologue: load + store tile 0 into stage 0 ----
    va[0] = *(const float4*)(A + (long long)rr0 * K + cc0);
    va[1] = *(const float4*)(A + (long long)rr1 * K + cc1);
    vb[0] = *(const float4*)(Bm + (long long)rr0 * K + cc0);
    vb[1] = *(const float4*)(Bm + (long long)rr1 * K + cc1);

    auto store_stage = [&](int s) {
        uint32_t* As = sm + s * STAGE;
        uint32_t* Bs = As + ARR;
        uint32_t* Al = As + 2 * ARR;
        uint32_t* Bl = As + 3 * ARR;
#pragma unroll
        for (int j = 0; j < 2; j++) {
            int rr = j ? rr1 : rr0;
            int cc = j ? cc1 : cc0;
            float4 v = va[j];
            uint32_t h0 = f2tf(v.x), h1 = f2tf(v.y), h2 = f2tf(v.z), h3 = f2tf(v.w);
            *(uint4*)(As + rr * LDSR + cc) = make_uint4(h0, h1, h2, h3);
            if (SPLIT) {
                *(uint4*)(Al + rr * LDSR + cc) = make_uint4(
                    f2tf(v.x - __uint_as_float(h0)), f2tf(v.y - __uint_as_float(h1)),
                    f2tf(v.z - __uint_as_float(h2)), f2tf(v.w - __uint_as_float(h3)));
            }
            v = vb[j];
            h0 = f2tf(v.x); h1 = f2tf(v.y); h2 = f2tf(v.z); h3 = f2tf(v.w);
            *(uint4*)(Bs + rr * LDSR + cc) = make_uint4(h0, h1, h2, h3);
            if (SPLIT) {
                *(uint4*)(Bl + rr * LDSR + cc) = make_uint4(
                    f2tf(v.x - __uint_as_float(h0)), f2tf(v.y - __uint_as_float(h1)),
                    f2tf(v.z - __uint_as_float(h2)), f2tf(v.w - __uint_as_float(h3)));
            }
        }
    };

    store_stage(0);
    __syncthreads();

    for (int t = 0; t < nk; t++) {
        // prefetch next tile into registers (latency hidden by MMA phase below)
        if (t + 1 < nk) {
            int kc = (t + 1) * BK;
            va[0] = *(const float4*)(A + (long long)rr0 * K + kc + cc0);
            va[1] = *(const float4*)(A + (long long)rr1 * K + kc + cc1);
            vb[0] = *(const float4*)(Bm + (long long)rr0 * K + kc + cc0);
            vb[1] = *(const float4*)(Bm + (long long)rr1 * K + kc + cc1);
        }

        // MMA on current stage (pure LDS + MMA)
        const uint32_t* As = sm + (t & 1) * STAGE;
        const uint32_t* Bs = As + ARR;
        const uint32_t* Al = As + 2 * ARR;
        const uint32_t* Bl = As + 3 * ARR;
#pragma unroll
        for (int ks = 0; ks < 2; ks++) {
            int k0 = ks * 8;
            uint32_t a[2][4], al[2][4];
#pragma unroll
            for (int i = 0; i < 2; i++) {
                int ro = (wm * 32 + i * 16 + grp) * LDSR + k0 + tq;
                a[i][0] = As[ro];
                a[i][1] = As[ro + 8 * LDSR];
                a[i][2] = As[ro + 4];
                a[i][3] = As[ro + 8 * LDSR + 4];
                if (SPLIT) {
                    al[i][0] = Al[ro];
                    al[i][1] = Al[ro + 8 * LDSR];
                    al[i][2] = Al[ro + 4];
                    al[i][3] = Al[ro + 8 * LDSR + 4];
                }
            }
#pragma unroll
            for (int j = 0; j < 8; j++) {
                int co = (wn * 64 + j * 8 + grp) * LDSR + k0 + tq;
                uint32_t b[2], bl2[2];
                b[0] = Bs[co];
                b[1] = Bs[co + 4];
                if (SPLIT) {
                    bl2[0] = Bl[co];
                    bl2[1] = Bl[co + 4];
                }
#pragma unroll
                for (int i = 0; i < 2; i++) {
                    if (SPLIT) {
                        MMA8(acc[i][j], al[i], b);
                        MMA8(acc[i][j], a[i], bl2);
                    }
                    MMA8(acc[i][j], a[i], b);
                }
            }
        }

        // convert + store prefetched tile into the other stage, then one sync
        if (t + 1 < nk) store_stage((t + 1) & 1);
        __syncthreads();
    }

    // epilogue
    int row0 = blockIdx.x * BM + wm * 32 + grp;
    int col0 = blockIdx.y * BN + wn * 64 + 2 * tq;
    float* C = Cptr + zb * sC;
    const float* R = RESID ? (Rptr + zb * sC) : nullptr;
#pragma unroll
    for (int i = 0; i < 2; i++) {
#pragma unroll
        for (int j = 0; j < 8; j++) {
            int row = row0 + i * 16;
            int col = col0 + j * 8;
            float2 v0 = make_float2(acc[i][j][0], acc[i][j][1]);
            float2 v1 = make_float2(acc[i][j][2], acc[i][j][3]);
            if (BIAS) {
                float2 bb = *(const float2*)(bias + col);
                v0.x += bb.x; v0.y += bb.y;
                v1.x += bb.x; v1.y += bb.y;
            }
            if (RESID) {
                float2 r0 = *(const float2*)(R + (long long)row * Ncols + col);
                float2 r1 = *(const float2*)(R + (long long)(row + 8) * Ncols + col);
                v0.x += r0.x; v0.y += r0.y;
                v1.x += r1.x; v1.y += r1.y;
            }
            if (SEG) {
                // cols 0..255 -> segment 0 (L), 256..511 -> segment 1 (G)
                float* cp0 = C + (long long)(col >> 8) * ((long long)NB * NM * ND)
                               + (long long)row * ND + (col & 255);
                *(float2*)cp0 = v0;
                *(float2*)(cp0 + 8LL * ND) = v1;
            } else {
                *(float2*)(C + (long long)row * Ncols + col) = v0;
                *(float2*)(C + (long long)(row + 8) * Ncols + col) = v1;
            }
        }
    }
}

// ---------------- softmax over M: one warp per row ----------------
__global__ void softmax_k(float* __restrict__ S) {
    int row = blockIdx.x * 8 + (threadIdx.x >> 5);
    int lane = threadIdx.x & 31;
    float4* p4 = (float4*)(S + (size_t)row * NM) + lane;
    float4 v[8];
    float mx = -1e30f;
#pragma unroll
    for (int t = 0; t < 8; t++) {
        v[t] = p4[t * 32];
        mx = fmaxf(mx, fmaxf(fmaxf(v[t].x, v[t].y), fmaxf(v[t].z, v[t].w)));
    }
#pragma unroll
    for (int o = 16; o > 0; o >>= 1) mx = fmaxf(mx, __shfl_xor_sync(0xffffffffu, mx, o));
    float sum = 0.f;
#pragma unroll
    for (int t = 0; t < 8; t++) {
        v[t].x = __expf(v[t].x - mx);
        v[t].y = __expf(v[t].y - mx);
        v[t].z = __expf(v[t].z - mx);
        v[t].w = __expf(v[t].w - mx);
        sum += v[t].x + v[t].y + v[t].z + v[t].w;
    }
#pragma unroll
    for (int o = 16; o > 0; o >>= 1) sum += __shfl_xor_sync(0xffffffffu, sum, o);
    float inv = 1.0f / sum;
#pragma unroll
    for (int t = 0; t < 8; t++) {
        v[t].x *= inv; v[t].y *= inv; v[t].z *= inv; v[t].w *= inv;
        p4[t * 32] = v[t];
    }
}

// ---------------- launch ----------------
extern "C" void kernel_launch(void* const* d_in, const int* in_sizes, int n_in,
                              void* d_out, int out_size) {
    const float* p  = (const float*)d_in[0];
    const float* r  = (const float*)d_in[1];
    // d_in[2] = batch ids (int64) — unused (implied by layout)
    const float* Wh = (const float*)d_in[3];
    const float* bh = (const float*)d_in[4];
    const float* Wl = (const float*)d_in[5];
    const float* bl = (const float*)d_in[6];
    const float* Wg = (const float*)d_in[7];
    const float* bg = (const float*)d_in[8];
    float* out = (float*)d_out;
    (void)in_sizes; (void)n_in; (void)out_size;

    float* s = nullptr;
    cudaGetSymbolAddress((void**)&s, g_scratch);
    float* WhT = s + OFF_WHT;
    float* WlT = s + OFF_WLT;   // WlT/WgT contiguous 512x256
    float* BLG = s + OFF_BLG;
    float* H   = s + OFF_H;
    float* L   = s + OFF_L;     // L/G contiguous
    float* G   = s + OFF_G;
    float* GT  = s + OFF_GT;
    float* S   = s + OFF_S;

    const int SMEM_SPLIT = 2 * 4 * 128 * 20 * 4;  // 81920: 2 stages x (As,Bs,Al,Bl)
    const int SMEM_PLAIN = 2 * 2 * 128 * 20 * 4;  // 40960: 2 stages x (As,Bs)
    cudaFuncSetAttribute(gemm_tt<true, true, false, false>,
                         cudaFuncAttributeMaxDynamicSharedMemorySize, SMEM_SPLIT);
    cudaFuncSetAttribute(gemm_tt<true, true, false, true>,
                         cudaFuncAttributeMaxDynamicSharedMemorySize, SMEM_SPLIT);
    cudaFuncSetAttribute(gemm_tt<true, false, false, false>,
                         cudaFuncAttributeMaxDynamicSharedMemorySize, SMEM_SPLIT);
    cudaFuncSetAttribute(gemm_tt<false, false, true, false>,
                         cudaFuncAttributeMaxDynamicSharedMemorySize, SMEM_PLAIN);

    // 0. transpose weights -> [n][k]; concat biases
    transpose_w_k<<<256, 256>>>(Wh, Wl, Wg, bl, bg, WhT, WlT, WlT + (size_t)ND * ND, BLG);

    // 1. H = p @ Wh + bh   (split-tf32; rows = B*N)
    gemm_tt<true, true, false, false><<<dim3(NB * NN / 128, ND / 128, 1), 256, SMEM_SPLIT>>>(
        p, WhT, bh, nullptr, H, ND, ND, 0, 0, 0);

    // 2+3. [L | G] = r @ [Wl | Wg] + [bl | bg]   (fused, split-tf32, segmented output)
    gemm_tt<true, true, false, true><<<dim3(NB * NM / 128, 2 * ND / 128, 1), 256, SMEM_SPLIT>>>(
        r, WlT, BLG, nullptr, L, ND, ND, 0, 0, 0);

    // 4. GT[b][d][m]
    transpose_g_k<<<dim3(NM / 32, ND / 32, NB), dim3(32, 8)>>>(G, GT);

    // 5. scores[b][n][m] = sum_d H[b,n,d] * L[b,m,d]   (split-tf32, batched)
    gemm_tt<true, false, false, false><<<dim3(NN / 128, NM / 128, NB), 256, SMEM_SPLIT>>>(
        H, L, nullptr, nullptr, S, ND, NM,
        (long long)NN * ND, (long long)NM * ND, (long long)NN * NM);

    // 6. softmax over M (in place)
    softmax_k<<<NB * NN / 8, 256>>>(S);

    // 7. out = p + attn @ G   (plain tf32 post-softmax; batched)
    gemm_tt<false, false, true, false><<<dim3(NN / 128, ND / 128, NB), 256, SMEM_PLAIN>>>(
        S, GT, nullptr, p, out, NM, ND,
        (long long)NN * NM, (long long)ND * NM, (long long)NN * ND);
}

// round 8
// speedup vs baseline: 1.4446x; 1.4446x over previous
#include <cuda_runtime.h>
#include <cuda_bf16.h>
#include <cuda_fp16.h>
#include <cstdint>

#define NB 8
#define NN 4096
#define NM 1024
#define ND 256

// ---------------- scratch (device globals; no runtime allocation) ----------------
static constexpr size_t OFF_WHT = 0;
static constexpr size_t OFF_WLT = OFF_WHT + (size_t)ND * ND;   // WlT then WgT contiguous (512x256)
static constexpr size_t OFF_WGT = OFF_WLT + (size_t)ND * ND;
static constexpr size_t OFF_BLG = OFF_WGT + (size_t)ND * ND;   // concat bias [bl|bg], 512
static constexpr size_t OFF_H   = OFF_BLG + 512;
static constexpr size_t OFF_L   = OFF_H  + (size_t)NB * NN * ND;  // L then G contiguous
static constexpr size_t OFF_G   = OFF_L  + (size_t)NB * NM * ND;
static constexpr size_t OFF_GT  = OFF_G  + (size_t)NB * NM * ND;  // fp16 GT (uses half the floats)
static constexpr size_t OFF_S   = OFF_GT + (size_t)NB * ND * NM;
static constexpr size_t OFF_P   = OFF_S  + (size_t)NB * NN * NM;  // fp16 attn, packed u32
static constexpr size_t SCRATCH_TOTAL = OFF_P + (size_t)NB * NN * NM / 2;

__device__ float g_scratch[SCRATCH_TOTAL];

// ---------------- helpers ----------------
__device__ __forceinline__ uint32_t f2tf(float x) {
    uint32_t r;
    asm("cvt.rna.tf32.f32 %0, %1;" : "=r"(r) : "f"(x));
    return r;
}

__device__ __forceinline__ uint32_t pack_bf(float x, float y) {
    __nv_bfloat162 t = __floats2bfloat162_rn(x, y);  // low = x
    return *(uint32_t*)&t;
}
__device__ __forceinline__ uint32_t pack_hf(float x, float y) {
    __half2 t = __floats2half2_rn(x, y);  // low = x
    return *(uint32_t*)&t;
}
__device__ __forceinline__ float bf_res(float x) {  // x - bf16(x)
    return x - __bfloat162float(__float2bfloat16_rn(x));
}

#define MMA8(d, a, b)                                                          \
    asm volatile(                                                              \
        "mma.sync.aligned.m16n8k8.row.col.f32.tf32.tf32.f32 "                  \
        "{%0,%1,%2,%3},{%4,%5,%6,%7},{%8,%9},{%0,%1,%2,%3};\n"                 \
        : "+f"((d)[0]), "+f"((d)[1]), "+f"((d)[2]), "+f"((d)[3])               \
        : "r"((a)[0]), "r"((a)[1]), "r"((a)[2]), "r"((a)[3]),                  \
          "r"((b)[0]), "r"((b)[1]))

#define MMA16B(d, a, b)                                                        \
    asm volatile(                                                              \
        "mma.sync.aligned.m16n8k16.row.col.f32.bf16.bf16.f32 "                 \
        "{%0,%1,%2,%3},{%4,%5,%6,%7},{%8,%9},{%0,%1,%2,%3};\n"                 \
        : "+f"((d)[0]), "+f"((d)[1]), "+f"((d)[2]), "+f"((d)[3])               \
        : "r"((a)[0]), "r"((a)[1]), "r"((a)[2]), "r"((a)[3]),                  \
          "r"((b)[0]), "r"((b)[1]))

#define MMA16H(d, a, b)                                                        \
    asm volatile(                                                              \
        "mma.sync.aligned.m16n8k16.row.col.f32.f16.f16.f32 "                   \
        "{%0,%1,%2,%3},{%4,%5,%6,%7},{%8,%9},{%0,%1,%2,%3};\n"                 \
        : "+f"((d)[0]), "+f"((d)[1]), "+f"((d)[2]), "+f"((d)[3])               \
        : "r"((a)[0]), "r"((a)[1]), "r"((a)[2]), "r"((a)[3]),                  \
          "r"((b)[0]), "r"((b)[1]))

// ---------------- weight transpose + bias concat ----------------
__global__ void transpose_w_k(const float* __restrict__ Wh,
                              const float* __restrict__ Wl,
                              const float* __restrict__ Wg,
                              const float* __restrict__ bl,
                              const float* __restrict__ bg,
                              float* __restrict__ wht,
                              float* __restrict__ wlt,
                              float* __restrict__ wgt,
                              float* __restrict__ blg) {
    int i = blockIdx.x * blockDim.x + threadIdx.x;  // 65536 total
    int n = i >> 8, k = i & 255;
    wht[i] = Wh[k * ND + n];
    wlt[i] = Wl[k * ND + n];
    wgt[i] = Wg[k * ND + n];
    if (i < 512) blg[i] = (i < 256) ? bl[i] : bg[i - 256];
}

// ---------------- G transpose -> fp16: GT[b][d][m] = fp16(G[b][m][d]) ----------------
__global__ void transpose_g_k(const float* __restrict__ G, __half* __restrict__ GT) {
    __shared__ float t[32][33];
    int b = blockIdx.z;
    int m0 = blockIdx.x * 32, d0 = blockIdx.y * 32;
    const float* src = G + (size_t)b * NM * ND;
    __half* dst = GT + (size_t)b * ND * NM;
    int x = threadIdx.x, y = threadIdx.y;
#pragma unroll
    for (int i = 0; i < 32; i += 8) t[y + i][x] = src[(size_t)(m0 + y + i) * ND + d0 + x];
    __syncthreads();
#pragma unroll
    for (int i = 0; i < 32; i += 8)
        dst[(size_t)(d0 + y + i) * NM + m0 + x] = __float2half_rn(t[x][y + i]);
}

// ---------------- split-tf32 TT GEMM (round-4 structure, known good) ----------------
// C[row][col] = sum_k A[row][k] * Bsrc[col][k]; conversion at cooperative store.
// SEG: cols 0..255 -> Cptr, 256..511 -> Cptr + NB*NM*ND (fused L/G output).
template <bool SPLIT, bool BIAS, bool RESID, bool SEG>
__global__ void __launch_bounds__(256)
gemm_tt(const float* __restrict__ Aptr, const float* __restrict__ Bptr,
        const float* __restrict__ bias, const float* __restrict__ Rptr,
        float* __restrict__ Cptr, int K, int Ncols,
        long long sA, long long sB, long long sC) {
    constexpr int BM = 128, BN = 128, BK = 32, LDSR = 36;
    extern __shared__ uint32_t smem_u[];
    uint32_t* As = smem_u;
    uint32_t* Bs = smem_u + BM * LDSR;
    uint32_t* Al = smem_u + 2 * BM * LDSR;
    uint32_t* Bl = smem_u + 3 * BM * LDSR;

    int tid = threadIdx.x;
    int lane = tid & 31, wid = tid >> 5;
    int wm = wid >> 1, wn = wid & 1;
    int grp = lane >> 2, tq = lane & 3;

    long long zb = blockIdx.z;
    const float* A = Aptr + zb * sA + (long long)blockIdx.x * BM * K;
    const float* Bm = Bptr + zb * sB + (long long)blockIdx.y * BN * K;

    float acc[2][8][4];
#pragma unroll
    for (int i = 0; i < 2; i++)
#pragma unroll
        for (int j = 0; j < 8; j++)
#pragma unroll
            for (int q = 0; q < 4; q++) acc[i][j][q] = 0.f;

    for (int kc = 0; kc < K; kc += BK) {
        __syncthreads();
#pragma unroll
        for (int it = 0; it < 4; it++) {
            int idx = tid + it * 256;
            int rr = idx >> 3, cc = (idx & 7) * 4;
            float4 va = *(const float4*)(A + (long long)rr * K + kc + cc);
            float4 vb = *(const float4*)(Bm + (long long)rr * K + kc + cc);
            uint32_t* pa = As + rr * LDSR + cc;
            uint32_t* pb = Bs + rr * LDSR + cc;
            uint32_t h;
            h = f2tf(va.x); pa[0] = h; if (SPLIT) Al[rr * LDSR + cc + 0] = f2tf(va.x - __uint_as_float(h));
            h = f2tf(va.y); pa[1] = h; if (SPLIT) Al[rr * LDSR + cc + 1] = f2tf(va.y - __uint_as_float(h));
            h = f2tf(va.z); pa[2] = h; if (SPLIT) Al[rr * LDSR + cc + 2] = f2tf(va.z - __uint_as_float(h));
            h = f2tf(va.w); pa[3] = h; if (SPLIT) Al[rr * LDSR + cc + 3] = f2tf(va.w - __uint_as_float(h));
            h = f2tf(vb.x); pb[0] = h; if (SPLIT) Bl[rr * LDSR + cc + 0] = f2tf(vb.x - __uint_as_float(h));
            h = f2tf(vb.y); pb[1] = h; if (SPLIT) Bl[rr * LDSR + cc + 1] = f2tf(vb.y - __uint_as_float(h));
            h = f2tf(vb.z); pb[2] = h; if (SPLIT) Bl[rr * LDSR + cc + 2] = f2tf(vb.z - __uint_as_float(h));
            h = f2tf(vb.w); pb[3] = h; if (SPLIT) Bl[rr * LDSR + cc + 3] = f2tf(vb.w - __uint_as_float(h));
        }
        __syncthreads();
#pragma unroll
        for (int ks = 0; ks < 4; ks++) {
            int k0 = ks * 8;
            uint32_t a[2][4], al[2][4];
            uint32_t b[8][2], bl2[8][2];
#pragma unroll
            for (int i = 0; i < 2; i++) {
                int ro = (wm * 32 + i * 16 + grp) * LDSR + k0 + tq;
                a[i][0] = As[ro];
                a[i][1] = As[ro + 8 * LDSR];
                a[i][2] = As[ro + 4];
                a[i][3] = As[ro + 8 * LDSR + 4];
                if (SPLIT) {
                    al[i][0] = Al[ro];
                    al[i][1] = Al[ro + 8 * LDSR];
                    al[i][2] = Al[ro + 4];
                    al[i][3] = Al[ro + 8 * LDSR + 4];
                }
            }
#pragma unroll
            for (int j = 0; j < 8; j++) {
                int co = (wn * 64 + j * 8 + grp) * LDSR + k0 + tq;
                b[j][0] = Bs[co];
                b[j][1] = Bs[co + 4];
                if (SPLIT) {
                    bl2[j][0] = Bl[co];
                    bl2[j][1] = Bl[co + 4];
                }
            }
#pragma unroll
            for (int i = 0; i < 2; i++)
#pragma unroll
                for (int j = 0; j < 8; j++) {
                    if (SPLIT) {
                        MMA8(acc[i][j], al[i], b[j]);
                        MMA8(acc[i][j], a[i], bl2[j]);
                    }
                    MMA8(acc[i][j], a[i], b[j]);
                }
        }
    }

    int row0 = blockIdx.x * BM + wm * 32 + grp;
    int col0 = blockIdx.y * BN + wn * 64 + 2 * tq;
    float* C = Cptr + zb * sC;
    const float* R = RESID ? (Rptr + zb * sC) : nullptr;
#pragma unroll
    for (int i = 0; i < 2; i++) {
#pragma unroll
        for (int j = 0; j < 8; j++) {
            int row = row0 + i * 16;
            int col = col0 + j * 8;
            float2 v0 = make_float2(acc[i][j][0], acc[i][j][1]);
            float2 v1 = make_float2(acc[i][j][2], acc[i][j][3]);
            if (BIAS) {
                float2 bb = *(const float2*)(bias + col);
                v0.x += bb.x; v0.y += bb.y;
                v1.x += bb.x; v1.y += bb.y;
            }
            if (RESID) {
                float2 r0 = *(const float2*)(R + (long long)row * Ncols + col);
                float2 r1 = *(const float2*)(R + (long long)(row + 8) * Ncols + col);
                v0.x += r0.x; v0.y += r0.y;
                v1.x += r1.x; v1.y += r1.y;
            }
            if (SEG) {
                float* cp0 = C + (long long)(col >> 8) * ((long long)NB * NM * ND)
                               + (long long)row * ND + (col & 255);
                *(float2*)cp0 = v0;
                *(float2*)(cp0 + 8LL * ND) = v1;
            } else {
                *(float2*)(C + (long long)row * Ncols + col) = v0;
                *(float2*)(C + (long long)(row + 8) * Ncols + col) = v1;
            }
        }
    }
}

// ---------------- 16-bit TT GEMM (round-4 structure, m16n8k16) ----------------
// SPLIT3: A,B fp32 in gmem, 3-term bf16 split (hi*hi + lo*hi + hi*lo) at store.
// !SPLIT3: A,B already fp16 (u32-packed pairs) in gmem; pure copy; 1 fp16 MMA.
// K is in LOGICAL elements (f32 count for SPLIT3; half count for plain).
template <bool SPLIT3, bool RESID>
__global__ void __launch_bounds__(256)
gemm_bf(const void* __restrict__ Aptr_, const void* __restrict__ Bptr_,
        const float* __restrict__ Rptr, float* __restrict__ Cptr,
        int K, int Ncols, long long sA, long long sB, long long sC) {
    constexpr int BM = 128, BN = 128, BK = 32, LDSR = 20;  // 16 u32 (32 x16) per row + pad
    constexpr int ARR = BM * LDSR;
    extern __shared__ uint32_t sm[];
    uint32_t* As = sm;
    uint32_t* Bs = sm + ARR;
    uint32_t* Al = sm + 2 * ARR;  // SPLIT3 only
    uint32_t* Bl = sm + 3 * ARR;

    int tid = threadIdx.x;
    int lane = tid & 31, wid = tid >> 5;
    int wm = wid >> 1, wn = wid & 1;
    int grp = lane >> 2, tq = lane & 3;

    long long zb = blockIdx.z;
    const float* Af = nullptr; const float* Bf = nullptr;
    const uint32_t* Au = nullptr; const uint32_t* Bu = nullptr;
    if (SPLIT3) {
        Af = (const float*)Aptr_ + zb * sA + (long long)blockIdx.x * BM * K;
        Bf = (const float*)Bptr_ + zb * sB + (long long)blockIdx.y * BN * K;
    } else {
        Au = (const uint32_t*)Aptr_ + zb * sA + (long long)blockIdx.x * BM * (K >> 1);
        Bu = (const uint32_t*)Bptr_ + zb * sB + (long long)blockIdx.y * BN * (K >> 1);
    }

    float acc[2][8][4];
#pragma unroll
    for (int i = 0; i < 2; i++)
#pragma unroll
        for (int j = 0; j < 8; j++)
#pragma unroll
            for (int q = 0; q < 4; q++) acc[i][j][q] = 0.f;

    for (int kc = 0; kc < K; kc += BK) {
        __syncthreads();
        if (SPLIT3) {
#pragma unroll
            for (int it = 0; it < 4; it++) {
                int idx = tid + it * 256;
                int rr = idx >> 3, cc = (idx & 7) * 4;
                int pc = cc >> 1;
                float4 va = *(const float4*)(Af + (long long)rr * K + kc + cc);
                float4 vb = *(const float4*)(Bf + (long long)rr * K + kc + cc);
                As[rr * LDSR + pc]     = pack_bf(va.x, va.y);
                As[rr * LDSR + pc + 1] = pack_bf(va.z, va.w);
                Al[rr * LDSR + pc]     = pack_bf(bf_res(va.x), bf_res(va.y));
                Al[rr * LDSR + pc + 1] = pack_bf(bf_res(va.z), bf_res(va.w));
                Bs[rr * LDSR + pc]     = pack_bf(vb.x, vb.y);
                Bs[rr * LDSR + pc + 1] = pack_bf(vb.z, vb.w);
                Bl[rr * LDSR + pc]     = pack_bf(bf_res(vb.x), bf_res(vb.y));
                Bl[rr * LDSR + pc + 1] = pack_bf(bf_res(vb.z), bf_res(vb.w));
            }
        } else {
#pragma unroll
            for (int it = 0; it < 2; it++) {
                int idx = tid + it * 256;
                int rr = idx >> 2, uc = (idx & 3) * 4;
                *(uint4*)(As + rr * LDSR + uc) =
                    *(const uint4*)(Au + (long long)rr * (K >> 1) + (kc >> 1) + uc);
                *(uint4*)(Bs + rr * LDSR + uc) =
                    *(const uint4*)(Bu + (long long)rr * (K >> 1) + (kc >> 1) + uc);
            }
        }
        __syncthreads();
#pragma unroll
        for (int ks = 0; ks < 2; ks++) {
            int kp = ks * 8;  // u32-pair offset (16 elems per ks step)
            uint32_t a[2][4], al[2][4];
#pragma unroll
            for (int i = 0; i < 2; i++) {
                int ro = (wm * 32 + i * 16 + grp) * LDSR + kp + tq;
                a[i][0] = As[ro];
                a[i][1] = As[ro + 8 * LDSR];
                a[i][2] = As[ro + 4];
                a[i][3] = As[ro + 8 * LDSR + 4];
                if (SPLIT3) {
                    al[i][0] = Al[ro];
                    al[i][1] = Al[ro + 8 * LDSR];
                    al[i][2] = Al[ro + 4];
                    al[i][3] = Al[ro + 8 * LDSR + 4];
                }
            }
#pragma unroll
            for (int j = 0; j < 8; j++) {
                int co = (wn * 64 + j * 8 + grp) * LDSR + kp + tq;
                uint32_t b[2], bl2[2];
                b[0] = Bs[co];
                b[1] = Bs[co + 4];
                if (SPLIT3) {
                    bl2[0] = Bl[co];
                    bl2[1] = Bl[co + 4];
                }
#pragma unroll
                for (int i = 0; i < 2; i++) {
                    if (SPLIT3) {
                        MMA16B(acc[i][j], al[i], b);
                        MMA16B(acc[i][j], a[i], bl2);
                        MMA16B(acc[i][j], a[i], b);
                    } else {
                        MMA16H(acc[i][j], a[i], b);
                    }
                }
            }
        }
    }

    int row0 = blockIdx.x * BM + wm * 32 + grp;
    int col0 = blockIdx.y * BN + wn * 64 + 2 * tq;
    float* C = Cptr + zb * sC;
    const float* R = RESID ? (Rptr + zb * sC) : nullptr;
#pragma unroll
    for (int i = 0; i < 2; i++) {
#pragma unroll
        for (int j = 0; j < 8; j++) {
            int row = row0 + i * 16;
            int col = col0 + j * 8;
            float2 v0 = make_float2(acc[i][j][0], acc[i][j][1]);
            float2 v1 = make_float2(acc[i][j][2], acc[i][j][3]);
            if (RESID) {
                float2 r0 = *(const float2*)(R + (long long)row * Ncols + col);
                float2 r1 = *(const float2*)(R + (long long)(row + 8) * Ncols + col);
                v0.x += r0.x; v0.y += r0.y;
                v1.x += r1.x; v1.y += r1.y;
            }
            *(float2*)(C + (long long)row * Ncols + col) = v0;
            *(float2*)(C + (long long)(row + 8) * Ncols + col) = v1;
        }
    }
}

// ---------------- softmax over M: read fp32 scores, write fp16 attn ----------------
__global__ void softmax_k(const float* __restrict__ S, uint32_t* __restrict__ P) {
    int row = blockIdx.x * 8 + (threadIdx.x >> 5);
    int lane = threadIdx.x & 31;
    const float4* p4 = (const float4*)(S + (size_t)row * NM) + lane;
    uint32_t* pb = P + (size_t)row * (NM / 2);
    float4 v[8];
    float mx = -1e30f;
#pragma unroll
    for (int t = 0; t < 8; t++) {
        v[t] = p4[t * 32];
        mx = fmaxf(mx, fmaxf(fmaxf(v[t].x, v[t].y), fmaxf(v[t].z, v[t].w)));
    }
#pragma unroll
    for (int o = 16; o > 0; o >>= 1) mx = fmaxf(mx, __shfl_xor_sync(0xffffffffu, mx, o));
    float sum = 0.f;
#pragma unroll
    for (int t = 0; t < 8; t++) {
        v[t].x = __expf(v[t].x - mx);
        v[t].y = __expf(v[t].y - mx);
        v[t].z = __expf(v[t].z - mx);
        v[t].w = __expf(v[t].w - mx);
        sum += v[t].x + v[t].y + v[t].z + v[t].w;
    }
#pragma unroll
    for (int o = 16; o > 0; o >>= 1) sum += __shfl_xor_sync(0xffffffffu, sum, o);
    float inv = 1.0f / sum;
#pragma unroll
    for (int t = 0; t < 8; t++) {
        uint2 w;
        w.x = pack_hf(v[t].x * inv, v[t].y * inv);
        w.y = pack_hf(v[t].z * inv, v[t].w * inv);
        *(uint2*)(pb + (lane + t * 32) * 2) = w;
    }
}

// ---------------- launch ----------------
extern "C" void kernel_launch(void* const* d_in, const int* in_sizes, int n_in,
                              void* d_out, int out_size) {
    const float* p  = (const float*)d_in[0];
    const float* r  = (const float*)d_in[1];
    // d_in[2] = batch ids (int64) — unused (implied by layout)
    const float* Wh = (const float*)d_in[3];
    const float* bh = (const float*)d_in[4];
    const float* Wl = (const float*)d_in[5];
    const float* bl = (const float*)d_in[6];
    const float* Wg = (const float*)d_in[7];
    const float* bg = (const float*)d_in[8];
    float* out = (float*)d_out;
    (void)in_sizes; (void)n_in; (void)out_size;

    float* s = nullptr;
    cudaGetSymbolAddress((void**)&s, g_scratch);
    float* WhT = s + OFF_WHT;
    float* WlT = s + OFF_WLT;
    float* BLG = s + OFF_BLG;
    float* H   = s + OFF_H;
    float* L   = s + OFF_L;
    float* G   = s + OFF_G;
    __half* GTh = (__half*)(s + OFF_GT);
    float* S   = s + OFF_S;
    uint32_t* P = (uint32_t*)(s + OFF_P);

    const int SMEM_TF32 = 4 * 128 * 36 * 4;   // 73728
    const int SMEM_BF3  = 4 * 128 * 20 * 4;   // 40960
    const int SMEM_HF1  = 2 * 128 * 20 * 4;   // 20480
    cudaFuncSetAttribute(gemm_tt<true, true, false, false>,
                         cudaFuncAttributeMaxDynamicSharedMemorySize, SMEM_TF32);
    cudaFuncSetAttribute(gemm_tt<true, true, false, true>,
                         cudaFuncAttributeMaxDynamicSharedMemorySize, SMEM_TF32);
    cudaFuncSetAttribute(gemm_bf<true, false>,
                         cudaFuncAttributeMaxDynamicSharedMemorySize, SMEM_BF3);
    cudaFuncSetAttribute(gemm_bf<false, true>,
                         cudaFuncAttributeMaxDynamicSharedMemorySize, SMEM_HF1);

    // 0. transpose weights -> [n][k]; concat biases
    transpose_w_k<<<256, 256>>>(Wh, Wl, Wg, bl, bg, WhT, WlT, WlT + (size_t)ND * ND, BLG);

    // 1. H = p @ Wh + bh   (split-tf32)
    gemm_tt<true, true, false, false><<<dim3(NB * NN / 128, ND / 128, 1), 256, SMEM_TF32>>>(
        p, WhT, bh, nullptr, H, ND, ND, 0, 0, 0);

    // 2+3. [L | G] = r @ [Wl | Wg] + [bl | bg]   (fused, split-tf32, segmented)
    gemm_tt<true, true, false, true><<<dim3(NB * NM / 128, 2 * ND / 128, 1), 256, SMEM_TF32>>>(
        r, WlT, BLG, nullptr, L, ND, ND, 0, 0, 0);

    // 4. GT[b][d][m] in fp16
    transpose_g_k<<<dim3(NM / 32, ND / 32, NB), dim3(32, 8)>>>(G, GTh);

    // 5. scores = H @ L^T   (bf16x3, batched, fp32 out)
    gemm_bf<true, false><<<dim3(NN / 128, NM / 128, NB), 256, SMEM_BF3>>>(
        H, L, nullptr, S, ND, NM,
        (long long)NN * ND, (long long)NM * ND, (long long)NN * NM);

    // 6. softmax over M -> fp16 attn P
    softmax_k<<<NB * NN / 8, 256>>>(S, P);

    // 7. out = p + attn @ G   (plain fp16, batched; A,B strides in u32)
    gemm_bf<false, true><<<dim3(NN / 128, ND / 128, NB), 256, SMEM_HF1>>>(
        P, GTh, p, out, NM, ND,
        (long long)NN * NM / 2, (long long)ND * NM / 2, (long long)NN * ND);
}

// round 9
// speedup vs baseline: 1.6146x; 1.1177x over previous
#include <cuda_runtime.h>
#include <cuda_bf16.h>
#include <cuda_fp16.h>
#include <cstdint>

#define NB 8
#define NN 4096
#define NM 1024
#define ND 256

// ---------------- scratch (device globals; no runtime allocation) ----------------
// sizes in float (=u32) slots
static constexpr size_t OFF_WHT = 0;
static constexpr size_t OFF_WLT = OFF_WHT + (size_t)ND * ND;   // WlT then WgT contiguous
static constexpr size_t OFF_WGT = OFF_WLT + (size_t)ND * ND;
static constexpr size_t OFF_BLG = OFF_WGT + (size_t)ND * ND;   // concat bias [bl|bg]
static constexpr size_t OFF_HHI = OFF_BLG + 512;                         // u32-packed bf16 pairs
static constexpr size_t OFF_HLO = OFF_HHI + (size_t)NB * NN * ND / 2;
static constexpr size_t OFF_LHI = OFF_HLO + (size_t)NB * NN * ND / 2;
static constexpr size_t OFF_LLO = OFF_LHI + (size_t)NB * NM * ND / 2;
static constexpr size_t OFF_G   = OFF_LLO + (size_t)NB * NM * ND / 2;    // fp32
static constexpr size_t OFF_GT  = OFF_G   + (size_t)NB * NM * ND;        // fp16 (half the slots)
static constexpr size_t OFF_S   = OFF_GT  + (size_t)NB * ND * NM / 2;    // fp32 scores
static constexpr size_t OFF_P   = OFF_S   + (size_t)NB * NN * NM;        // fp16 attn pairs
static constexpr size_t SCRATCH_TOTAL = OFF_P + (size_t)NB * NN * NM / 2;

__device__ float g_scratch[SCRATCH_TOTAL];

// ---------------- helpers ----------------
__device__ __forceinline__ uint32_t f2tf(float x) {
    uint32_t r;
    asm("cvt.rna.tf32.f32 %0, %1;" : "=r"(r) : "f"(x));
    return r;
}
__device__ __forceinline__ uint32_t pack_bf(float x, float y) {
    __nv_bfloat162 t = __floats2bfloat162_rn(x, y);  // low = x
    return *(uint32_t*)&t;
}
__device__ __forceinline__ uint32_t pack_hf(float x, float y) {
    __half2 t = __floats2half2_rn(x, y);  // low = x
    return *(uint32_t*)&t;
}
__device__ __forceinline__ float bf_res(float x) {  // x - bf16(x)
    return x - __bfloat162float(__float2bfloat16_rn(x));
}
__device__ __forceinline__ void cp16(uint32_t dst, const void* src) {
    asm volatile("cp.async.cg.shared.global [%0], [%1], 16;" :: "r"(dst), "l"(src));
}

#define MMA8(d, a, b)                                                          \
    asm volatile(                                                              \
        "mma.sync.aligned.m16n8k8.row.col.f32.tf32.tf32.f32 "                  \
        "{%0,%1,%2,%3},{%4,%5,%6,%7},{%8,%9},{%0,%1,%2,%3};\n"                 \
        : "+f"((d)[0]), "+f"((d)[1]), "+f"((d)[2]), "+f"((d)[3])               \
        : "r"((a)[0]), "r"((a)[1]), "r"((a)[2]), "r"((a)[3]),                  \
          "r"((b)[0]), "r"((b)[1]))

#define MMA16B(d, a, b)                                                        \
    asm volatile(                                                              \
        "mma.sync.aligned.m16n8k16.row.col.f32.bf16.bf16.f32 "                 \
        "{%0,%1,%2,%3},{%4,%5,%6,%7},{%8,%9},{%0,%1,%2,%3};\n"                 \
        : "+f"((d)[0]), "+f"((d)[1]), "+f"((d)[2]), "+f"((d)[3])               \
        : "r"((a)[0]), "r"((a)[1]), "r"((a)[2]), "r"((a)[3]),                  \
          "r"((b)[0]), "r"((b)[1]))

#define MMA16H(d, a, b)                                                        \
    asm volatile(                                                              \
        "mma.sync.aligned.m16n8k16.row.col.f32.f16.f16.f32 "                   \
        "{%0,%1,%2,%3},{%4,%5,%6,%7},{%8,%9},{%0,%1,%2,%3};\n"                 \
        : "+f"((d)[0]), "+f"((d)[1]), "+f"((d)[2]), "+f"((d)[3])               \
        : "r"((a)[0]), "r"((a)[1]), "r"((a)[2]), "r"((a)[3]),                  \
          "r"((b)[0]), "r"((b)[1]))

// ---------------- weight transpose + bias concat ----------------
__global__ void transpose_w_k(const float* __restrict__ Wh,
                              const float* __restrict__ Wl,
                              const float* __restrict__ Wg,
                              const float* __restrict__ bl,
                              const float* __restrict__ bg,
                              float* __restrict__ wht,
                              float* __restrict__ wlt,
                              float* __restrict__ wgt,
                              float* __restrict__ blg) {
    int i = blockIdx.x * blockDim.x + threadIdx.x;  // 65536 total
    int n = i >> 8, k = i & 255;
    wht[i] = Wh[k * ND + n];
    wlt[i] = Wl[k * ND + n];
    wgt[i] = Wg[k * ND + n];
    if (i < 512) blg[i] = (i < 256) ? bl[i] : bg[i - 256];
}

// ---------------- G transpose -> fp16: GT[b][d][m] = fp16(G[b][m][d]) ----------------
__global__ void transpose_g_k(const float* __restrict__ G, __half* __restrict__ GT) {
    __shared__ float t[32][33];
    int b = blockIdx.z;
    int m0 = blockIdx.x * 32, d0 = blockIdx.y * 32;
    const float* src = G + (size_t)b * NM * ND;
    __half* dst = GT + (size_t)b * ND * NM;
    int x = threadIdx.x, y = threadIdx.y;
#pragma unroll
    for (int i = 0; i < 32; i += 8) t[y + i][x] = src[(size_t)(m0 + y + i) * ND + d0 + x];
    __syncthreads();
#pragma unroll
    for (int i = 0; i < 32; i += 8)
        dst[(size_t)(d0 + y + i) * NM + m0 + x] = __float2half_rn(t[x][y + i]);
}

// ---------------- split-tf32 TT GEMM (round-4 loop), bf16-pair-packing epilogue ----------
// C[row][col] = sum_k A[row][k] * B[col][k] + bias[col]
// OUT==1: all cols packed -> Chi/Clo u32 pairs, row stride Ncols/2.
// OUT==2: cols 0..255 packed -> Chi/Clo (row stride 128); cols 256..511 -> Cg fp32 (stride 256).
template <bool BIAS, int OUT>
__global__ void __launch_bounds__(256)
gemm_tt(const float* __restrict__ Aptr, const float* __restrict__ Bptr,
        const float* __restrict__ bias,
        uint32_t* __restrict__ Chi, uint32_t* __restrict__ Clo,
        float* __restrict__ Cg, int K, int Ncols) {
    constexpr int BM = 128, BN = 128, BK = 32, LDSR = 36;
    extern __shared__ uint32_t smem_u[];
    uint32_t* As = smem_u;
    uint32_t* Bs = smem_u + BM * LDSR;
    uint32_t* Al = smem_u + 2 * BM * LDSR;
    uint32_t* Bl = smem_u + 3 * BM * LDSR;

    int tid = threadIdx.x;
    int lane = tid & 31, wid = tid >> 5;
    int wm = wid >> 1, wn = wid & 1;
    int grp = lane >> 2, tq = lane & 3;

    const float* A = Aptr + (long long)blockIdx.x * BM * K;
    const float* Bm = Bptr + (long long)blockIdx.y * BN * K;

    float acc[2][8][4];
#pragma unroll
    for (int i = 0; i < 2; i++)
#pragma unroll
        for (int j = 0; j < 8; j++)
#pragma unroll
            for (int q = 0; q < 4; q++) acc[i][j][q] = 0.f;

    for (int kc = 0; kc < K; kc += BK) {
        __syncthreads();
#pragma unroll
        for (int it = 0; it < 4; it++) {
            int idx = tid + it * 256;
            int rr = idx >> 3, cc = (idx & 7) * 4;
            float4 va = *(const float4*)(A + (long long)rr * K + kc + cc);
            float4 vb = *(const float4*)(Bm + (long long)rr * K + kc + cc);
            uint32_t* pa = As + rr * LDSR + cc;
            uint32_t* pb = Bs + rr * LDSR + cc;
            uint32_t h;
            h = f2tf(va.x); pa[0] = h; Al[rr * LDSR + cc + 0] = f2tf(va.x - __uint_as_float(h));
            h = f2tf(va.y); pa[1] = h; Al[rr * LDSR + cc + 1] = f2tf(va.y - __uint_as_float(h));
            h = f2tf(va.z); pa[2] = h; Al[rr * LDSR + cc + 2] = f2tf(va.z - __uint_as_float(h));
            h = f2tf(va.w); pa[3] = h; Al[rr * LDSR + cc + 3] = f2tf(va.w - __uint_as_float(h));
            h = f2tf(vb.x); pb[0] = h; Bl[rr * LDSR + cc + 0] = f2tf(vb.x - __uint_as_float(h));
            h = f2tf(vb.y); pb[1] = h; Bl[rr * LDSR + cc + 1] = f2tf(vb.y - __uint_as_float(h));
            h = f2tf(vb.z); pb[2] = h; Bl[rr * LDSR + cc + 2] = f2tf(vb.z - __uint_as_float(h));
            h = f2tf(vb.w); pb[3] = h; Bl[rr * LDSR + cc + 3] = f2tf(vb.w - __uint_as_float(h));
        }
        __syncthreads();
#pragma unroll
        for (int ks = 0; ks < 4; ks++) {
            int k0 = ks * 8;
            uint32_t a[2][4], al[2][4];
            uint32_t b[8][2], bl2[8][2];
#pragma unroll
            for (int i = 0; i < 2; i++) {
                int ro = (wm * 32 + i * 16 + grp) * LDSR + k0 + tq;
                a[i][0] = As[ro];
                a[i][1] = As[ro + 8 * LDSR];
                a[i][2] = As[ro + 4];
                a[i][3] = As[ro + 8 * LDSR + 4];
                al[i][0] = Al[ro];
                al[i][1] = Al[ro + 8 * LDSR];
                al[i][2] = Al[ro + 4];
                al[i][3] = Al[ro + 8 * LDSR + 4];
            }
#pragma unroll
            for (int j = 0; j < 8; j++) {
                int co = (wn * 64 + j * 8 + grp) * LDSR + k0 + tq;
                b[j][0] = Bs[co];
                b[j][1] = Bs[co + 4];
                bl2[j][0] = Bl[co];
                bl2[j][1] = Bl[co + 4];
            }
#pragma unroll
            for (int i = 0; i < 2; i++)
#pragma unroll
                for (int j = 0; j < 8; j++) {
                    MMA8(acc[i][j], al[i], b[j]);
                    MMA8(acc[i][j], a[i], bl2[j]);
                    MMA8(acc[i][j], a[i], b[j]);
                }
        }
    }

    // epilogue: pack bf16 hi/lo pairs (cols (col,col+1) are consecutive in each acc half)
    int row0 = blockIdx.x * BM + wm * 32 + grp;
    int col0 = blockIdx.y * BN + wn * 64 + 2 * tq;
#pragma unroll
    for (int i = 0; i < 2; i++) {
#pragma unroll
        for (int j = 0; j < 8; j++) {
            int row = row0 + i * 16;
            int col = col0 + j * 8;
            float2 v0 = make_float2(acc[i][j][0], acc[i][j][1]);
            float2 v1 = make_float2(acc[i][j][2], acc[i][j][3]);
            if (BIAS) {
                float2 bb = *(const float2*)(bias + col);
                v0.x += bb.x; v0.y += bb.y;
                v1.x += bb.x; v1.y += bb.y;
            }
            if (OUT == 1 || (OUT == 2 && col < 256)) {
                int pr = (OUT == 1) ? (Ncols >> 1) : 128;
                long long i0 = (long long)row * pr + (col >> 1);
                long long i1 = (long long)(row + 8) * pr + (col >> 1);
                Chi[i0] = pack_bf(v0.x, v0.y);
                Clo[i0] = pack_bf(bf_res(v0.x), bf_res(v0.y));
                Chi[i1] = pack_bf(v1.x, v1.y);
                Clo[i1] = pack_bf(bf_res(v1.x), bf_res(v1.y));
            } else {  // OUT==2, G segment: fp32
                int gc = col - 256;
                *(float2*)(Cg + (long long)row * 256 + gc) = v0;
                *(float2*)(Cg + (long long)(row + 8) * 256 + gc) = v1;
            }
        }
    }
}

// ---------------- 16-bit GEMM, pure-copy cp.async double-buffered ----------------
// MODE 1 (scores): A/B pre-packed bf16 hi/lo pairs; 3x MMA16B. fp32 out.
// MODE 0 (out):    A/B fp16 pairs; 1x MMA16H; +RESID fp32 residual.
// Kp = u32 pairs per row. All strides in u32 units (sC in f32).
template <int MODE, bool RESID>
__global__ void __launch_bounds__(256)
gemm_bf(const uint32_t* __restrict__ Ahi, const uint32_t* __restrict__ Alo,
        const uint32_t* __restrict__ Bhi, const uint32_t* __restrict__ Blo,
        const float* __restrict__ Rptr, float* __restrict__ Cptr,
        int Kp, int Ncols, long long sA, long long sB, long long sC) {
    constexpr int BM = 128, BN = 128, BKP = 16, LDSR = 20;  // 16 u32 pairs/row + pad
    constexpr int ARR = BM * LDSR;
    constexpr int NARR = (MODE == 1) ? 4 : 2;
    constexpr int STAGE = NARR * ARR;
    extern __shared__ uint32_t sm[];
    uint32_t sbase = (uint32_t)__cvta_generic_to_shared(sm);

    int tid = threadIdx.x;
    int lane = tid & 31, wid = tid >> 5;
    int wm = wid >> 1, wn = wid & 1;
    int grp = lane >> 2, tq = lane & 3;

    long long zb = blockIdx.z;
    const uint32_t* Ah = Ahi + zb * sA + (long long)blockIdx.x * BM * Kp;
    const uint32_t* Bh = Bhi + zb * sB + (long long)blockIdx.y * BN * Kp;
    const uint32_t* Al_g = (MODE == 1) ? Alo + zb * sA + (long long)blockIdx.x * BM * Kp : nullptr;
    const uint32_t* Bl_g = (MODE == 1) ? Blo + zb * sB + (long long)blockIdx.y * BN * Kp : nullptr;

    float acc[2][8][4];
#pragma unroll
    for (int i = 0; i < 2; i++)
#pragma unroll
        for (int j = 0; j < 8; j++)
#pragma unroll
            for (int q = 0; q < 4; q++) acc[i][j][q] = 0.f;

    const int nk = Kp / BKP;

    // per-thread copy slots: 512 float4 per (128x16 u32) array; 2 per thread per array
    int rr0 = tid >> 2, uc0 = (tid & 3) * 4;
    int rr1 = (tid + 256) >> 2, uc1 = ((tid + 256) & 3) * 4;

    auto issue = [&](int stage, int kcp) {
        uint32_t dA = sbase + (uint32_t)stage * STAGE * 4;
        uint32_t dB = dA + ARR * 4;
        uint32_t o0 = (uint32_t)(rr0 * LDSR + uc0) * 4;
        uint32_t o1 = (uint32_t)(rr1 * LDSR + uc1) * 4;
        cp16(dA + o0, Ah + (long long)rr0 * Kp + kcp + uc0);
        cp16(dA + o1, Ah + (long long)rr1 * Kp + kcp + uc1);
        cp16(dB + o0, Bh + (long long)rr0 * Kp + kcp + uc0);
        cp16(dB + o1, Bh + (long long)rr1 * Kp + kcp + uc1);
        if (MODE == 1) {
            uint32_t dAl = dA + 2 * ARR * 4;
            uint32_t dBl = dA + 3 * ARR * 4;
            cp16(dAl + o0, Al_g + (long long)rr0 * Kp + kcp + uc0);
            cp16(dAl + o1, Al_g + (long long)rr1 * Kp + kcp + uc1);
            cp16(dBl + o0, Bl_g + (long long)rr0 * Kp + kcp + uc0);
            cp16(dBl + o1, Bl_g + (long long)rr1 * Kp + kcp + uc1);
        }
        asm volatile("cp.async.commit_group;");
    };

    issue(0, 0);
    asm volatile("cp.async.wait_group 0;");
    __syncthreads();

    for (int t = 0; t < nk; t++) {
        int cur = t & 1;
        if (t + 1 < nk) issue(1 - cur, (t + 1) * BKP);

        const uint32_t* As = sm + cur * STAGE;
        const uint32_t* Bs = As + ARR;
        const uint32_t* Al = As + 2 * ARR;
        const uint32_t* Bl = As + 3 * ARR;
#pragma unroll
        for (int ks = 0; ks < 2; ks++) {
            int kp = ks * 8;
            uint32_t a[2][4], al[2][4];
#pragma unroll
            for (int i = 0; i < 2; i++) {
                int ro = (wm * 32 + i * 16 + grp) * LDSR + kp + tq;
                a[i][0] = As[ro];
                a[i][1] = As[ro + 8 * LDSR];
                a[i][2] = As[ro + 4];
                a[i][3] = As[ro + 8 * LDSR + 4];
                if (MODE == 1) {
                    al[i][0] = Al[ro];
                    al[i][1] = Al[ro + 8 * LDSR];
                    al[i][2] = Al[ro + 4];
                    al[i][3] = Al[ro + 8 * LDSR + 4];
                }
            }
#pragma unroll
            for (int j = 0; j < 8; j++) {
                int co = (wn * 64 + j * 8 + grp) * LDSR + kp + tq;
                uint32_t b[2], bl2[2];
                b[0] = Bs[co];
                b[1] = Bs[co + 4];
                if (MODE == 1) {
                    bl2[0] = Bl[co];
                    bl2[1] = Bl[co + 4];
                }
#pragma unroll
                for (int i = 0; i < 2; i++) {
                    if (MODE == 1) {
                        MMA16B(acc[i][j], al[i], b);
                        MMA16B(acc[i][j], a[i], bl2);
                        MMA16B(acc[i][j], a[i], b);
                    } else {
                        MMA16H(acc[i][j], a[i], b);
                    }
                }
            }
        }
        if (t + 1 < nk) asm volatile("cp.async.wait_group 0;");
        __syncthreads();
    }

    int row0 = blockIdx.x * BM + wm * 32 + grp;
    int col0 = blockIdx.y * BN + wn * 64 + 2 * tq;
    float* C = Cptr + zb * sC;
    const float* R = RESID ? (Rptr + zb * sC) : nullptr;
#pragma unroll
    for (int i = 0; i < 2; i++) {
#pragma unroll
        for (int j = 0; j < 8; j++) {
            int row = row0 + i * 16;
            int col = col0 + j * 8;
            float2 v0 = make_float2(acc[i][j][0], acc[i][j][1]);
            float2 v1 = make_float2(acc[i][j][2], acc[i][j][3]);
            if (RESID) {
                float2 r0 = *(const float2*)(R + (long long)row * Ncols + col);
                float2 r1 = *(const float2*)(R + (long long)(row + 8) * Ncols + col);
                v0.x += r0.x; v0.y += r0.y;
                v1.x += r1.x; v1.y += r1.y;
            }
            *(float2*)(C + (long long)row * Ncols + col) = v0;
            *(float2*)(C + (long long)(row + 8) * Ncols + col) = v1;
        }
    }
}

// ---------------- softmax over M: read fp32 scores, write fp16 attn ----------------
__global__ void softmax_k(const float* __restrict__ S, uint32_t* __restrict__ P) {
    int row = blockIdx.x * 8 + (threadIdx.x >> 5);
    int lane = threadIdx.x & 31;
    const float4* p4 = (const float4*)(S + (size_t)row * NM) + lane;
    uint32_t* pb = P + (size_t)row * (NM / 2);
    float4 v[8];
    float mx = -1e30f;
#pragma unroll
    for (int t = 0; t < 8; t++) {
        v[t] = p4[t * 32];
        mx = fmaxf(mx, fmaxf(fmaxf(v[t].x, v[t].y), fmaxf(v[t].z, v[t].w)));
    }
#pragma unroll
    for (int o = 16; o > 0; o >>= 1) mx = fmaxf(mx, __shfl_xor_sync(0xffffffffu, mx, o));
    float sum = 0.f;
#pragma unroll
    for (int t = 0; t < 8; t++) {
        v[t].x = __expf(v[t].x - mx);
        v[t].y = __expf(v[t].y - mx);
        v[t].z = __expf(v[t].z - mx);
        v[t].w = __expf(v[t].w - mx);
        sum += v[t].x + v[t].y + v[t].z + v[t].w;
    }
#pragma unroll
    for (int o = 16; o > 0; o >>= 1) sum += __shfl_xor_sync(0xffffffffu, sum, o);
    float inv = 1.0f / sum;
#pragma unroll
    for (int t = 0; t < 8; t++) {
        uint2 w;
        w.x = pack_hf(v[t].x * inv, v[t].y * inv);
        w.y = pack_hf(v[t].z * inv, v[t].w * inv);
        *(uint2*)(pb + (lane + t * 32) * 2) = w;
    }
}

// ---------------- launch ----------------
extern "C" void kernel_launch(void* const* d_in, const int* in_sizes, int n_in,
                              void* d_out, int out_size) {
    const float* p  = (const float*)d_in[0];
    const float* r  = (const float*)d_in[1];
    // d_in[2] = batch ids (int64) — unused (implied by layout)
    const float* Wh = (const float*)d_in[3];
    const float* bh = (const float*)d_in[4];
    const float* Wl = (const float*)d_in[5];
    const float* bl = (const float*)d_in[6];
    const float* Wg = (const float*)d_in[7];
    const float* bg = (const float*)d_in[8];
    float* out = (float*)d_out;
    (void)in_sizes; (void)n_in; (void)out_size;

    float* s = nullptr;
    cudaGetSymbolAddress((void**)&s, g_scratch);
    float* WhT = s + OFF_WHT;
    float* WlT = s + OFF_WLT;
    float* BLG = s + OFF_BLG;
    uint32_t* Hhi = (uint32_t*)(s + OFF_HHI);
    uint32_t* Hlo = (uint32_t*)(s + OFF_HLO);
    uint32_t* Lhi = (uint32_t*)(s + OFF_LHI);
    uint32_t* Llo = (uint32_t*)(s + OFF_LLO);
    float* G   = s + OFF_G;
    __half* GTh = (__half*)(s + OFF_GT);
    float* S   = s + OFF_S;
    uint32_t* P = (uint32_t*)(s + OFF_P);

    const int SMEM_TF32 = 4 * 128 * 36 * 4;       // 73728
    const int SMEM_SC   = 2 * 4 * 128 * 20 * 4;   // 81920 (2 stages x 4 arrays)
    const int SMEM_OUT  = 2 * 2 * 128 * 20 * 4;   // 40960
    cudaFuncSetAttribute(gemm_tt<true, 1>,
                         cudaFuncAttributeMaxDynamicSharedMemorySize, SMEM_TF32);
    cudaFuncSetAttribute(gemm_tt<true, 2>,
                         cudaFuncAttributeMaxDynamicSharedMemorySize, SMEM_TF32);
    cudaFuncSetAttribute(gemm_bf<1, false>,
                         cudaFuncAttributeMaxDynamicSharedMemorySize, SMEM_SC);
    cudaFuncSetAttribute(gemm_bf<0, true>,
                         cudaFuncAttributeMaxDynamicSharedMemorySize, SMEM_OUT);

    // 0. transpose weights -> [n][k]; concat biases
    transpose_w_k<<<256, 256>>>(Wh, Wl, Wg, bl, bg, WhT, WlT, WlT + (size_t)ND * ND, BLG);

    // 1. H = p @ Wh + bh  (split-tf32) -> packed bf16 hi/lo pairs
    gemm_tt<true, 1><<<dim3(NB * NN / 128, ND / 128, 1), 256, SMEM_TF32>>>(
        p, WhT, bh, Hhi, Hlo, nullptr, ND, ND);

    // 2+3. [L | G] = r @ [Wl | Wg] + [bl | bg]  (split-tf32; L packed bf16, G fp32)
    gemm_tt<true, 2><<<dim3(NB * NM / 128, 2 * ND / 128, 1), 256, SMEM_TF32>>>(
        r, WlT, BLG, Lhi, Llo, G, ND, 2 * ND);

    // 4. GT[b][d][m] in fp16
    transpose_g_k<<<dim3(NM / 32, ND / 32, NB), dim3(32, 8)>>>(G, GTh);

    // 5. scores = H @ L^T  (bf16x3 from pre-packed operands, cp.async pipelined)
    gemm_bf<1, false><<<dim3(NN / 128, NM / 128, NB), 256, SMEM_SC>>>(
        Hhi, Hlo, Lhi, Llo, nullptr, S, ND / 2, NM,
        (long long)NN * (ND / 2), (long long)NM * (ND / 2), (long long)NN * NM);

    // 6. softmax over M -> fp16 attn P
    softmax_k<<<NB * NN / 8, 256>>>(S, P);

    // 7. out = p + attn @ G  (fp16, cp.async pipelined)
    gemm_bf<0, true><<<dim3(NN / 128, ND / 128, NB), 256, SMEM_OUT>>>(
        P, nullptr, (const uint32_t*)GTh, nullptr, p, out, NM / 2, ND,
        (long long)NN * (NM / 2), (long long)ND * (NM / 2), (long long)NN * ND);
}

// round 10
// speedup vs baseline: 1.7609x; 1.0906x over previous
#include <cuda_runtime.h>
#include <cuda_bf16.h>
#include <cuda_fp16.h>
#include <cstdint>

#define NB 8
#define NN 4096
#define NM 1024
#define ND 256

// ---------------- scratch (device globals; no runtime allocation) ----------------
static constexpr size_t OFF_WHT = 0;
static constexpr size_t OFF_WLT = OFF_WHT + (size_t)ND * ND;
static constexpr size_t OFF_WGT = OFF_WLT + (size_t)ND * ND;
static constexpr size_t OFF_BLG = OFF_WGT + (size_t)ND * ND;
static constexpr size_t OFF_HHI = OFF_BLG + 512;                       // u32 bf16 pairs
static constexpr size_t OFF_HLO = OFF_HHI + (size_t)NB * NN * ND / 2;
static constexpr size_t OFF_LHI = OFF_HLO + (size_t)NB * NN * ND / 2;
static constexpr size_t OFF_LLO = OFF_LHI + (size_t)NB * NM * ND / 2;
static constexpr size_t OFF_G   = OFF_LLO + (size_t)NB * NM * ND / 2;  // fp32
static constexpr size_t OFF_GT  = OFF_G   + (size_t)NB * NM * ND;      // fp16 [B,D,M]
static constexpr size_t SCRATCH_TOTAL = OFF_GT + (size_t)NB * ND * NM / 2;

__device__ float g_scratch[SCRATCH_TOTAL];

// ---------------- helpers ----------------
__device__ __forceinline__ uint32_t f2tf(float x) {
    uint32_t r;
    asm("cvt.rna.tf32.f32 %0, %1;" : "=r"(r) : "f"(x));
    return r;
}
__device__ __forceinline__ uint32_t pack_bf(float x, float y) {
    __nv_bfloat162 t = __floats2bfloat162_rn(x, y);  // low = x
    return *(uint32_t*)&t;
}
__device__ __forceinline__ uint32_t pack_hf(float x, float y) {
    __half2 t = __floats2half2_rn(x, y);  // low = x
    return *(uint32_t*)&t;
}
__device__ __forceinline__ float bf_res(float x) {
    return x - __bfloat162float(__float2bfloat16_rn(x));
}
__device__ __forceinline__ void cp16(uint32_t dst, const void* src) {
    asm volatile("cp.async.cg.shared.global [%0], [%1], 16;" :: "r"(dst), "l"(src));
}

#define MMA8(d, a, b)                                                          \
    asm volatile(                                                              \
        "mma.sync.aligned.m16n8k8.row.col.f32.tf32.tf32.f32 "                  \
        "{%0,%1,%2,%3},{%4,%5,%6,%7},{%8,%9},{%0,%1,%2,%3};\n"                 \
        : "+f"((d)[0]), "+f"((d)[1]), "+f"((d)[2]), "+f"((d)[3])               \
        : "r"((a)[0]), "r"((a)[1]), "r"((a)[2]), "r"((a)[3]),                  \
          "r"((b)[0]), "r"((b)[1]))

#define MMA16B(d, a, b)                                                        \
    asm volatile(                                                              \
        "mma.sync.aligned.m16n8k16.row.col.f32.bf16.bf16.f32 "                 \
        "{%0,%1,%2,%3},{%4,%5,%6,%7},{%8,%9},{%0,%1,%2,%3};\n"                 \
        : "+f"((d)[0]), "+f"((d)[1]), "+f"((d)[2]), "+f"((d)[3])               \
        : "r"((a)[0]), "r"((a)[1]), "r"((a)[2]), "r"((a)[3]),                  \
          "r"((b)[0]), "r"((b)[1]))

#define MMA16H(d, a, b)                                                        \
    asm volatile(                                                              \
        "mma.sync.aligned.m16n8k16.row.col.f32.f16.f16.f32 "                   \
        "{%0,%1,%2,%3},{%4,%5,%6,%7},{%8,%9},{%0,%1,%2,%3};\n"                 \
        : "+f"((d)[0]), "+f"((d)[1]), "+f"((d)[2]), "+f"((d)[3])               \
        : "r"((a)[0]), "r"((a)[1]), "r"((a)[2]), "r"((a)[3]),                  \
          "r"((b)[0]), "r"((b)[1]))

// ---------------- weight transpose + bias concat ----------------
__global__ void transpose_w_k(const float* __restrict__ Wh,
                              const float* __restrict__ Wl,
                              const float* __restrict__ Wg,
                              const float* __restrict__ bl,
                              const float* __restrict__ bg,
                              float* __restrict__ wht,
                              float* __restrict__ wlt,
                              float* __restrict__ wgt,
                              float* __restrict__ blg) {
    int i = blockIdx.x * blockDim.x + threadIdx.x;
    int n = i >> 8, k = i & 255;
    wht[i] = Wh[k * ND + n];
    wlt[i] = Wl[k * ND + n];
    wgt[i] = Wg[k * ND + n];
    if (i < 512) blg[i] = (i < 256) ? bl[i] : bg[i - 256];
}

// ---------------- G transpose -> fp16: GT[b][d][m] ----------------
__global__ void transpose_g_k(const float* __restrict__ G, __half* __restrict__ GT) {
    __shared__ float t[32][33];
    int b = blockIdx.z;
    int m0 = blockIdx.x * 32, d0 = blockIdx.y * 32;
    const float* src = G + (size_t)b * NM * ND;
    __half* dst = GT + (size_t)b * ND * NM;
    int x = threadIdx.x, y = threadIdx.y;
#pragma unroll
    for (int i = 0; i < 32; i += 8) t[y + i][x] = src[(size_t)(m0 + y + i) * ND + d0 + x];
    __syncthreads();
#pragma unroll
    for (int i = 0; i < 32; i += 8)
        dst[(size_t)(d0 + y + i) * NM + m0 + x] = __float2half_rn(t[x][y + i]);
}

// ---------------- split-tf32 TT GEMM with bf16-pair packing epilogue ----------------
// OUT==1: all cols -> Chi/Clo pairs (row stride Ncols/2).
// OUT==2: cols 0..255 -> Chi/Clo (stride 128); cols 256..511 -> Cg fp32 (stride 256).
template <bool BIAS, int OUT>
__global__ void __launch_bounds__(256)
gemm_tt(const float* __restrict__ Aptr, const float* __restrict__ Bptr,
        const float* __restrict__ bias,
        uint32_t* __restrict__ Chi, uint32_t* __restrict__ Clo,
        float* __restrict__ Cg, int K, int Ncols) {
    constexpr int BM = 128, BN = 128, BK = 32, LDSR = 36;
    extern __shared__ uint32_t smem_u[];
    uint32_t* As = smem_u;
    uint32_t* Bs = smem_u + BM * LDSR;
    uint32_t* Al = smem_u + 2 * BM * LDSR;
    uint32_t* Bl = smem_u + 3 * BM * LDSR;

    int tid = threadIdx.x;
    int lane = tid & 31, wid = tid >> 5;
    int wm = wid >> 1, wn = wid & 1;
    int grp = lane >> 2, tq = lane & 3;

    const float* A = Aptr + (long long)blockIdx.x * BM * K;
    const float* Bm = Bptr + (long long)blockIdx.y * BN * K;

    float acc[2][8][4];
#pragma unroll
    for (int i = 0; i < 2; i++)
#pragma unroll
        for (int j = 0; j < 8; j++)
#pragma unroll
            for (int q = 0; q < 4; q++) acc[i][j][q] = 0.f;

    for (int kc = 0; kc < K; kc += BK) {
        __syncthreads();
#pragma unroll
        for (int it = 0; it < 4; it++) {
            int idx = tid + it * 256;
            int rr = idx >> 3, cc = (idx & 7) * 4;
            float4 va = *(const float4*)(A + (long long)rr * K + kc + cc);
            float4 vb = *(const float4*)(Bm + (long long)rr * K + kc + cc);
            uint32_t* pa = As + rr * LDSR + cc;
            uint32_t* pb = Bs + rr * LDSR + cc;
            uint32_t h;
            h = f2tf(va.x); pa[0] = h; Al[rr * LDSR + cc + 0] = f2tf(va.x - __uint_as_float(h));
            h = f2tf(va.y); pa[1] = h; Al[rr * LDSR + cc + 1] = f2tf(va.y - __uint_as_float(h));
            h = f2tf(va.z); pa[2] = h; Al[rr * LDSR + cc + 2] = f2tf(va.z - __uint_as_float(h));
            h = f2tf(va.w); pa[3] = h; Al[rr * LDSR + cc + 3] = f2tf(va.w - __uint_as_float(h));
            h = f2tf(vb.x); pb[0] = h; Bl[rr * LDSR + cc + 0] = f2tf(vb.x - __uint_as_float(h));
            h = f2tf(vb.y); pb[1] = h; Bl[rr * LDSR + cc + 1] = f2tf(vb.y - __uint_as_float(h));
            h = f2tf(vb.z); pb[2] = h; Bl[rr * LDSR + cc + 2] = f2tf(vb.z - __uint_as_float(h));
            h = f2tf(vb.w); pb[3] = h; Bl[rr * LDSR + cc + 3] = f2tf(vb.w - __uint_as_float(h));
        }
        __syncthreads();
#pragma unroll
        for (int ks = 0; ks < 4; ks++) {
            int k0 = ks * 8;
            uint32_t a[2][4], al[2][4];
            uint32_t b[8][2], bl2[8][2];
#pragma unroll
            for (int i = 0; i < 2; i++) {
                int ro = (wm * 32 + i * 16 + grp) * LDSR + k0 + tq;
                a[i][0] = As[ro];
                a[i][1] = As[ro + 8 * LDSR];
                a[i][2] = As[ro + 4];
                a[i][3] = As[ro + 8 * LDSR + 4];
                al[i][0] = Al[ro];
                al[i][1] = Al[ro + 8 * LDSR];
                al[i][2] = Al[ro + 4];
                al[i][3] = Al[ro + 8 * LDSR + 4];
            }
#pragma unroll
            for (int j = 0; j < 8; j++) {
                int co = (wn * 64 + j * 8 + grp) * LDSR + k0 + tq;
                b[j][0] = Bs[co];
                b[j][1] = Bs[co + 4];
                bl2[j][0] = Bl[co];
                bl2[j][1] = Bl[co + 4];
            }
#pragma unroll
            for (int i = 0; i < 2; i++)
#pragma unroll
                for (int j = 0; j < 8; j++) {
                    MMA8(acc[i][j], al[i], b[j]);
                    MMA8(acc[i][j], a[i], bl2[j]);
                    MMA8(acc[i][j], a[i], b[j]);
                }
        }
    }

    int row0 = blockIdx.x * BM + wm * 32 + grp;
    int col0 = blockIdx.y * BN + wn * 64 + 2 * tq;
#pragma unroll
    for (int i = 0; i < 2; i++) {
#pragma unroll
        for (int j = 0; j < 8; j++) {
            int row = row0 + i * 16;
            int col = col0 + j * 8;
            float2 v0 = make_float2(acc[i][j][0], acc[i][j][1]);
            float2 v1 = make_float2(acc[i][j][2], acc[i][j][3]);
            if (BIAS) {
                float2 bb = *(const float2*)(bias + col);
                v0.x += bb.x; v0.y += bb.y;
                v1.x += bb.x; v1.y += bb.y;
            }
            if (OUT == 1 || (OUT == 2 && col < 256)) {
                int pr = (OUT == 1) ? (Ncols >> 1) : 128;
                long long i0 = (long long)row * pr + (col >> 1);
                long long i1 = (long long)(row + 8) * pr + (col >> 1);
                Chi[i0] = pack_bf(v0.x, v0.y);
                Clo[i0] = pack_bf(bf_res(v0.x), bf_res(v0.y));
                Chi[i1] = pack_bf(v1.x, v1.y);
                Clo[i1] = pack_bf(bf_res(v1.x), bf_res(v1.y));
            } else {
                int gc = col - 256;
                *(float2*)(Cg + (long long)row * 256 + gc) = v0;
                *(float2*)(Cg + (long long)(row + 8) * 256 + gc) = v1;
            }
        }
    }
}

// ---------------- fused scores+softmax+out (flash-style) ----------------
// CTA = 128 query rows of one batch; loop over 8 M-tiles of 128.
// Warp layout 8x1: warp owns 16 rows x all cols -> softmax is quad-local.
// scores: bf16x3 from pre-packed H/L pairs (round-9 pipeline); attn reused
// as fp16 A-fragments directly from registers; out acc fp32 across all M.
__global__ void __launch_bounds__(256, 1)
fused_attn(const uint32_t* __restrict__ Hhi, const uint32_t* __restrict__ Hlo,
           const uint32_t* __restrict__ Lhi, const uint32_t* __restrict__ Llo,
           const uint32_t* __restrict__ Gt,  // fp16 pairs [B,256,512] u32
           const float* __restrict__ p, float* __restrict__ out) {
    constexpr int LDSR = 20, ARR = 128 * LDSR, STAGE = 4 * ARR;  // u32
    constexpr int LDG = 68;                                       // sG row stride (mod 32 == 4)
    extern __shared__ uint32_t sm[];
    uint32_t* sG = sm + 2 * STAGE;  // 256 x 68 u32 (GT tile, fp16 pairs)
    uint32_t sbase = (uint32_t)__cvta_generic_to_shared(sm);
    uint32_t gbase = sbase + 2 * STAGE * 4;

    int tid = threadIdx.x;
    int lane = tid & 31, wid = tid >> 5;
    int grp = lane >> 2, tq = lane & 3;
    int bx = blockIdx.x, zb = blockIdx.z;

    const uint32_t* Ah = Hhi + ((long long)zb * NN + bx * 128) * 128;
    const uint32_t* Alg = Hlo + ((long long)zb * NN + bx * 128) * 128;
    const uint32_t* Bh_b = Lhi + (long long)zb * NM * 128;
    const uint32_t* Bl_b = Llo + (long long)zb * NM * 128;
    const uint32_t* Gtb = Gt + (long long)zb * 256 * 512;

    // copy slots: A/B tiles (128x16 u32): 512 cp16, 2/thread
    int rr0 = tid >> 2, uc0 = (tid & 3) * 4;
    int rr1 = (tid + 256) >> 2, uc1 = ((tid + 256) & 3) * 4;

    float o[32][4];
#pragma unroll
    for (int j = 0; j < 32; j++)
#pragma unroll
        for (int q = 0; q < 4; q++) o[j][q] = 0.f;
    float m0 = -1e30f, m1 = -1e30f, s0 = 0.f, s1 = 0.f;

    for (int mt = 0; mt < 8; mt++) {
        const uint32_t* Bh = Bh_b + (long long)mt * 128 * 128;
        const uint32_t* Bl = Bl_b + (long long)mt * 128 * 128;

        auto issue = [&](int st, int kcp, int ch) {
            uint32_t dA = sbase + (uint32_t)st * STAGE * 4;
            uint32_t dB = dA + ARR * 4;
            uint32_t dAl = dA + 2 * ARR * 4;
            uint32_t dBl = dA + 3 * ARR * 4;
            uint32_t o0 = (uint32_t)(rr0 * LDSR + uc0) * 4;
            uint32_t o1 = (uint32_t)(rr1 * LDSR + uc1) * 4;
            cp16(dA + o0, Ah + (long long)rr0 * 128 + kcp + uc0);
            cp16(dA + o1, Ah + (long long)rr1 * 128 + kcp + uc1);
            cp16(dAl + o0, Alg + (long long)rr0 * 128 + kcp + uc0);
            cp16(dAl + o1, Alg + (long long)rr1 * 128 + kcp + uc1);
            cp16(dB + o0, Bh + (long long)rr0 * 128 + kcp + uc0);
            cp16(dB + o1, Bh + (long long)rr1 * 128 + kcp + uc1);
            cp16(dBl + o0, Bl + (long long)rr0 * 128 + kcp + uc0);
            cp16(dBl + o1, Bl + (long long)rr1 * 128 + kcp + uc1);
            // GT tile: 4096 cp16 total, 2 per thread per chunk
            int g = ch * 512 + tid * 2;
            int gr = g >> 4, gc = (g & 15) * 4;
            cp16(gbase + (uint32_t)(gr * LDG + gc) * 4, Gtb + (long long)gr * 512 + mt * 64 + gc);
            g++; gr = g >> 4; gc = (g & 15) * 4;
            cp16(gbase + (uint32_t)(gr * LDG + gc) * 4, Gtb + (long long)gr * 512 + mt * 64 + gc);
            asm volatile("cp.async.commit_group;");
        };

        float c[16][4];
#pragma unroll
        for (int j = 0; j < 16; j++)
#pragma unroll
            for (int q = 0; q < 4; q++) c[j][q] = 0.f;

        // ---- phase A: scores tile (cp.async double-buffered) ----
        issue(0, 0, 0);
        asm volatile("cp.async.wait_group 0;");
        __syncthreads();
        for (int t = 0; t < 8; t++) {
            if (t + 1 < 8) issue((t + 1) & 1, (t + 1) * 16, t + 1);
            const uint32_t* As = sm + (t & 1) * STAGE;
            const uint32_t* Bs = As + ARR;
            const uint32_t* Al = As + 2 * ARR;
            const uint32_t* Blo2 = As + 3 * ARR;
#pragma unroll
            for (int ks = 0; ks < 2; ks++) {
                int kp = ks * 8;
                uint32_t a[4], al[4];
                int ro = (wid * 16 + grp) * LDSR + kp + tq;
                a[0] = As[ro];
                a[1] = As[ro + 8 * LDSR];
                a[2] = As[ro + 4];
                a[3] = As[ro + 8 * LDSR + 4];
                al[0] = Al[ro];
                al[1] = Al[ro + 8 * LDSR];
                al[2] = Al[ro + 4];
                al[3] = Al[ro + 8 * LDSR + 4];
#pragma unroll
                for (int j = 0; j < 16; j++) {
                    int co = (j * 8 + grp) * LDSR + kp + tq;
                    uint32_t b[2], bl2[2];
                    b[0] = Bs[co];
                    b[1] = Bs[co + 4];
                    bl2[0] = Blo2[co];
                    bl2[1] = Blo2[co + 4];
                    MMA16B(c[j], al, b);
                    MMA16B(c[j], a, bl2);
                    MMA16B(c[j], a, b);
                }
            }
            if (t + 1 < 8) asm volatile("cp.async.wait_group 0;");
            __syncthreads();
        }

        // ---- phase B: online softmax (quad-local) ----
        float mx0 = -1e30f, mx1 = -1e30f;
#pragma unroll
        for (int j = 0; j < 16; j++) {
            mx0 = fmaxf(mx0, fmaxf(c[j][0], c[j][1]));
            mx1 = fmaxf(mx1, fmaxf(c[j][2], c[j][3]));
        }
        mx0 = fmaxf(mx0, __shfl_xor_sync(0xffffffffu, mx0, 1));
        mx0 = fmaxf(mx0, __shfl_xor_sync(0xffffffffu, mx0, 2));
        mx1 = fmaxf(mx1, __shfl_xor_sync(0xffffffffu, mx1, 1));
        mx1 = fmaxf(mx1, __shfl_xor_sync(0xffffffffu, mx1, 2));
        float nm0 = fmaxf(m0, mx0), nm1 = fmaxf(m1, mx1);
        float sc0 = __expf(m0 - nm0), sc1 = __expf(m1 - nm1);
        m0 = nm0; m1 = nm1;
        s0 *= sc0; s1 *= sc1;
#pragma unroll
        for (int j = 0; j < 32; j++) {
            o[j][0] *= sc0; o[j][1] *= sc0;
            o[j][2] *= sc1; o[j][3] *= sc1;
        }
#pragma unroll
        for (int j = 0; j < 16; j++) {
            c[j][0] = __expf(c[j][0] - m0);
            c[j][1] = __expf(c[j][1] - m0);
            c[j][2] = __expf(c[j][2] - m1);
            c[j][3] = __expf(c[j][3] - m1);
            s0 += c[j][0] + c[j][1];
            s1 += c[j][2] + c[j][3];
        }

        // ---- phase C: out += attn @ GT-tile (attn from registers) ----
#pragma unroll
        for (int kt = 0; kt < 8; kt++) {
            uint32_t a[4];
            a[0] = pack_hf(c[2 * kt][0], c[2 * kt][1]);
            a[1] = pack_hf(c[2 * kt][2], c[2 * kt][3]);
            a[2] = pack_hf(c[2 * kt + 1][0], c[2 * kt + 1][1]);
            a[3] = pack_hf(c[2 * kt + 1][2], c[2 * kt + 1][3]);
#pragma unroll
            for (int j = 0; j < 32; j++) {
                int co = (j * 8 + grp) * LDG + kt * 8 + tq;
                uint32_t b[2];
                b[0] = sG[co];
                b[1] = sG[co + 4];
                MMA16H(o[j], a, b);
            }
        }
        __syncthreads();  // protect stages + sG before next tile's copies
    }

    // ---- epilogue: normalize, add residual, store ----
    s0 += __shfl_xor_sync(0xffffffffu, s0, 1);
    s0 += __shfl_xor_sync(0xffffffffu, s0, 2);
    s1 += __shfl_xor_sync(0xffffffffu, s1, 1);
    s1 += __shfl_xor_sync(0xffffffffu, s1, 2);
    float inv0 = 1.0f / s0, inv1 = 1.0f / s1;

    int r0 = bx * 128 + wid * 16 + grp;
    float* ob = out + ((long long)zb * NN + r0) * ND;
    const float* pb = p + ((long long)zb * NN + r0) * ND;
#pragma unroll
    for (int j = 0; j < 32; j++) {
        int col = j * 8 + 2 * tq;
        float2 v0 = make_float2(o[j][0] * inv0 + pb[col], o[j][1] * inv0 + pb[col + 1]);
        float2 v1 = make_float2(o[j][2] * inv1 + pb[8 * ND + col],
                                o[j][3] * inv1 + pb[8 * ND + col + 1]);
        *(float2*)(ob + col) = v0;
        *(float2*)(ob + 8 * ND + col) = v1;
    }
}

// ---------------- launch ----------------
extern "C" void kernel_launch(void* const* d_in, const int* in_sizes, int n_in,
                              void* d_out, int out_size) {
    const float* p  = (const float*)d_in[0];
    const float* r  = (const float*)d_in[1];
    // d_in[2] = batch ids (int64) — unused (implied by layout)
    const float* Wh = (const float*)d_in[3];
    const float* bh = (const float*)d_in[4];
    const float* Wl = (const float*)d_in[5];
    const float* bl = (const float*)d_in[6];
    const float* Wg = (const float*)d_in[7];
    const float* bg = (const float*)d_in[8];
    float* out = (float*)d_out;
    (void)in_sizes; (void)n_in; (void)out_size;

    float* s = nullptr;
    cudaGetSymbolAddress((void**)&s, g_scratch);
    float* WhT = s + OFF_WHT;
    float* WlT = s + OFF_WLT;
    float* BLG = s + OFF_BLG;
    uint32_t* Hhi = (uint32_t*)(s + OFF_HHI);
    uint32_t* Hlo = (uint32_t*)(s + OFF_HLO);
    uint32_t* Lhi = (uint32_t*)(s + OFF_LHI);
    uint32_t* Llo = (uint32_t*)(s + OFF_LLO);
    float* G   = s + OFF_G;
    __half* GTh = (__half*)(s + OFF_GT);

    const int SMEM_TF32 = 4 * 128 * 36 * 4;                    // 73728
    const int SMEM_FUSED = 2 * 4 * 128 * 20 * 4 + 256 * 68 * 4;  // 81920 + 69632 = 151552
    cudaFuncSetAttribute(gemm_tt<true, 1>,
                         cudaFuncAttributeMaxDynamicSharedMemorySize, SMEM_TF32);
    cudaFuncSetAttribute(gemm_tt<true, 2>,
                         cudaFuncAttributeMaxDynamicSharedMemorySize, SMEM_TF32);
    cudaFuncSetAttribute(fused_attn,
                         cudaFuncAttributeMaxDynamicSharedMemorySize, SMEM_FUSED);

    // 0. transpose weights; concat biases
    transpose_w_k<<<256, 256>>>(Wh, Wl, Wg, bl, bg, WhT, WlT, WlT + (size_t)ND * ND, BLG);

    // 1. H = p @ Wh + bh  -> packed bf16 hi/lo pairs
    gemm_tt<true, 1><<<dim3(NB * NN / 128, ND / 128, 1), 256, SMEM_TF32>>>(
        p, WhT, bh, Hhi, Hlo, nullptr, ND, ND);

    // 2+3. [L | G] = r @ [Wl | Wg] + [bl | bg]  (L packed bf16, G fp32)
    gemm_tt<true, 2><<<dim3(NB * NM / 128, 2 * ND / 128, 1), 256, SMEM_TF32>>>(
        r, WlT, BLG, Lhi, Llo, G, ND, 2 * ND);

    // 4. GT[b][d][m] fp16
    transpose_g_k<<<dim3(NM / 32, ND / 32, NB), dim3(32, 8)>>>(G, GTh);

    // 5. fused: out = p + softmax(H L^T) @ G
    fused_attn<<<dim3(NN / 128, 1, NB), 256, SMEM_FUSED>>>(
        Hhi, Hlo, Lhi, Llo, (const uint32_t*)GTh, p, out);
}